// round 1
// baseline (speedup 1.0000x reference)
#include <cuda_runtime.h>
#include <cuda_bf16.h>

#define N_CELL  60000
#define N_GENE  4000
#define DIM     128
#define E_EDGES 1500000
#define EPS_BN  1e-5f
#define BM      64
#define BK      16

// ---------------- scratch (static __device__, no allocation) ----------------
__device__ int   g_hist[N_CELL];
__device__ int   g_off [N_CELL + 1];
__device__ int   g_cur [N_CELL];
__device__ int   g_csr [E_EDGES];
__device__ float g_agg [(size_t)N_CELL * DIM];
__device__ float g_colsum[DIM];
__device__ float g_colsq [DIM];
__device__ float g_mu [DIM];
__device__ float g_rs [DIM];

// ---------------- 0: zero counters/stats ----------------
__global__ void k_zero() {
    int i = blockIdx.x * blockDim.x + threadIdx.x;
    if (i < N_CELL) g_hist[i] = 0;
    if (i < DIM) { g_colsum[i] = 0.f; g_colsq[i] = 0.f; }
}

// ---------------- 1: histogram of edge destinations ----------------
__global__ void k_hist(const int* __restrict__ dst) {
    int i = blockIdx.x * blockDim.x + threadIdx.x;
    if (i < E_EDGES) atomicAdd(&g_hist[dst[i]], 1);
}

// ---------------- 2: exclusive scan over 60000 counts (1 block) ----------------
__global__ void k_scan() {
    __shared__ int wsum[32];
    __shared__ int carry;
    int t = threadIdx.x;          // 1024 threads
    int lane = t & 31, wid = t >> 5;
    if (t == 0) { carry = 0; g_off[0] = 0; }
    __syncthreads();
    for (int base = 0; base < N_CELL; base += 1024) {
        int i = base + t;
        int v = (i < N_CELL) ? g_hist[i] : 0;
        int x = v;
        #pragma unroll
        for (int o = 1; o < 32; o <<= 1) {
            int y = __shfl_up_sync(0xffffffffu, x, o);
            if (lane >= o) x += y;
        }
        if (lane == 31) wsum[wid] = x;
        __syncthreads();
        if (wid == 0) {
            int w = wsum[lane];
            #pragma unroll
            for (int o = 1; o < 32; o <<= 1) {
                int y = __shfl_up_sync(0xffffffffu, w, o);
                if (lane >= o) w += y;
            }
            wsum[lane] = w;
        }
        __syncthreads();
        int incl = x + (wid ? wsum[wid - 1] : 0) + carry;
        if (i < N_CELL) { g_off[i + 1] = incl; g_cur[i] = incl - v; }
        __syncthreads();
        if (t == 1023) carry = incl;
        __syncthreads();
    }
}

// ---------------- 3: scatter edge source ids into CSR ----------------
__global__ void k_scatter(const int* __restrict__ src, const int* __restrict__ dst) {
    int i = blockIdx.x * blockDim.x + threadIdx.x;
    if (i < E_EDGES) {
        int d = dst[i];
        int p = atomicAdd(&g_cur[d], 1);
        g_csr[p] = src[i];
    }
}

// ---------------- 4: per-cell neighbor mean (1 warp / cell) ----------------
__global__ void k_aggsum(const float* __restrict__ x_gene) {
    int w    = (blockIdx.x * blockDim.x + threadIdx.x) >> 5;
    int lane = threadIdx.x & 31;
    if (w >= N_CELL) return;
    int s = g_off[w], e = g_off[w + 1];
    const float4* xg = (const float4*)x_gene;
    float4 acc0 = {0.f, 0.f, 0.f, 0.f};
    float4 acc1 = {0.f, 0.f, 0.f, 0.f};
    int i = s;
    // 2-way unroll for MLP
    for (; i + 1 < e; i += 2) {
        int g0 = __ldg(&g_csr[i]);
        int g1 = __ldg(&g_csr[i + 1]);
        float4 v0 = __ldg(&xg[(size_t)g0 * 32 + lane]);
        float4 v1 = __ldg(&xg[(size_t)g1 * 32 + lane]);
        acc0.x += v0.x; acc0.y += v0.y; acc0.z += v0.z; acc0.w += v0.w;
        acc1.x += v1.x; acc1.y += v1.y; acc1.z += v1.z; acc1.w += v1.w;
    }
    if (i < e) {
        int g0 = __ldg(&g_csr[i]);
        float4 v0 = __ldg(&xg[(size_t)g0 * 32 + lane]);
        acc0.x += v0.x; acc0.y += v0.y; acc0.z += v0.z; acc0.w += v0.w;
    }
    float inv = 1.f / (float)max(e - s, 1);
    float4 r;
    r.x = (acc0.x + acc1.x) * inv;
    r.y = (acc0.y + acc1.y) * inv;
    r.z = (acc0.z + acc1.z) * inv;
    r.w = (acc0.w + acc1.w) * inv;
    ((float4*)g_agg)[(size_t)w * 32 + lane] = r;
}

// ---------------- 5: fused GEMM (agg@Wl + x_cell@Wr) + BN stats ----------------
// virtual K=256: k<128 -> (g_agg, Wl), k>=128 -> (x_cell, Wr). Bias skipped (BN cancels it).
__global__ __launch_bounds__(256) void k_gemm(
    const float* __restrict__ x_cell,
    const float* __restrict__ Wl,
    const float* __restrict__ Wr,
    float* __restrict__ out)
{
    __shared__ float As[BK][68];     // padded, [k][m]
    __shared__ float Bs[BK][DIM];    // [k][n]
    __shared__ float Rs[2][8][DIM];  // epilogue column reduction

    int tid = threadIdx.x;
    int tc = tid & 31;   // column group: 4 cols each
    int tr = tid >> 5;   // row group: 8 rows each
    int m0 = blockIdx.x * BM;

    float acc[8][4];
    #pragma unroll
    for (int r = 0; r < 8; r++)
        #pragma unroll
        for (int c = 0; c < 4; c++) acc[r][c] = 0.f;

    int arow = tid >> 2, aq = tid & 3;   // A-load mapping: 64 rows x 4 quads

    for (int kt = 0; kt < 16; kt++) {
        const float* Ap; const float* Bp; int k0;
        if (kt < 8) { Ap = g_agg;  Bp = Wl; k0 = kt * BK; }
        else        { Ap = x_cell; Bp = Wr; k0 = kt * BK - 128; }

        // A tile: 64x16, one float4 per thread, stored transposed
        int gm = m0 + arow;
        float4 av = {0.f, 0.f, 0.f, 0.f};
        if (gm < N_CELL)
            av = *(const float4*)&Ap[(size_t)gm * DIM + k0 + aq * 4];
        As[aq * 4 + 0][arow] = av.x;
        As[aq * 4 + 1][arow] = av.y;
        As[aq * 4 + 2][arow] = av.z;
        As[aq * 4 + 3][arow] = av.w;

        // B tile: 16x128, two float4 per thread
        #pragma unroll
        for (int r = 0; r < 2; r++) {
            int i = tid + r * 256;           // f4 index 0..511
            int bk = i >> 5, bn4 = i & 31;
            *(float4*)&Bs[bk][bn4 * 4] =
                *(const float4*)&Bp[(size_t)(k0 + bk) * DIM + bn4 * 4];
        }
        __syncthreads();

        #pragma unroll
        for (int kk = 0; kk < BK; kk++) {
            float4 a0 = *(const float4*)&As[kk][tr * 8];
            float4 a1 = *(const float4*)&As[kk][tr * 8 + 4];
            float4 b  = *(const float4*)&Bs[kk][tc * 4];
            float a[8] = {a0.x, a0.y, a0.z, a0.w, a1.x, a1.y, a1.z, a1.w};
            float bb[4] = {b.x, b.y, b.z, b.w};
            #pragma unroll
            for (int r = 0; r < 8; r++)
                #pragma unroll
                for (int c = 0; c < 4; c++)
                    acc[r][c] += a[r] * bb[c];
        }
        __syncthreads();
    }

    // epilogue: store + per-column sum/sumsq
    float s[4] = {0.f, 0.f, 0.f, 0.f};
    float q[4] = {0.f, 0.f, 0.f, 0.f};
    #pragma unroll
    for (int r = 0; r < 8; r++) {
        int gm = m0 + tr * 8 + r;
        if (gm < N_CELL) {
            float4 o = {acc[r][0], acc[r][1], acc[r][2], acc[r][3]};
            *(float4*)&out[(size_t)gm * DIM + tc * 4] = o;
            #pragma unroll
            for (int c = 0; c < 4; c++) {
                s[c] += acc[r][c];
                q[c] += acc[r][c] * acc[r][c];
            }
        }
    }
    #pragma unroll
    for (int c = 0; c < 4; c++) {
        Rs[0][tr][tc * 4 + c] = s[c];
        Rs[1][tr][tc * 4 + c] = q[c];
    }
    __syncthreads();
    if (tid < DIM) {
        float ss = 0.f, qq = 0.f;
        #pragma unroll
        for (int r = 0; r < 8; r++) { ss += Rs[0][r][tid]; qq += Rs[1][r][tid]; }
        atomicAdd(&g_colsum[tid], ss);
        atomicAdd(&g_colsq[tid], qq);
    }
}

// ---------------- 6: finalize BN stats ----------------
__global__ void k_bnstats() {
    int n = threadIdx.x;
    if (n < DIM) {
        float mu  = g_colsum[n] / (float)N_CELL;
        float var = g_colsq[n] / (float)N_CELL - mu * mu;
        g_mu[n] = mu;
        g_rs[n] = rsqrtf(var + EPS_BN);
    }
}

// ---------------- 7: normalize in place ----------------
__global__ void k_norm(float* __restrict__ out) {
    int i = blockIdx.x * blockDim.x + threadIdx.x;   // float4 index
    const int total = N_CELL * DIM / 4;
    if (i < total) {
        float4 v  = ((float4*)out)[i];
        int c4 = i & 31;
        float4 mu = ((const float4*)g_mu)[c4];
        float4 rs = ((const float4*)g_rs)[c4];
        v.x = (v.x - mu.x) * rs.x;
        v.y = (v.y - mu.y) * rs.y;
        v.z = (v.z - mu.z) * rs.z;
        v.w = (v.w - mu.w) * rs.w;
        ((float4*)out)[i] = v;
    }
}

// ---------------- launch ----------------
extern "C" void kernel_launch(void* const* d_in, const int* in_sizes, int n_in,
                              void* d_out, int out_size) {
    const float* x_cell = (const float*)d_in[0];
    const float* x_gene = (const float*)d_in[1];
    const float* Wl_gc  = (const float*)d_in[2];
    // d_in[3] = bl_gc (bias cancels under BatchNorm -> unused)
    const float* Wr_gc  = (const float*)d_in[4];
    // d_in[5..7] = cg-layer weights (dead code in reference)
    const int* gc_src = (const int*)d_in[8];
    const int* gc_dst = (const int*)d_in[9];
    // d_in[10..11] = cg edges (dead)
    float* out = (float*)d_out;

    const float* Wl = Wl_gc + DIM * DIM;   // layer index L-1 = 1
    const float* Wr = Wr_gc + DIM * DIM;

    k_zero   <<<(N_CELL + 255) / 256, 256>>>();
    k_hist   <<<(E_EDGES + 255) / 256, 256>>>(gc_dst);
    k_scan   <<<1, 1024>>>();
    k_scatter<<<(E_EDGES + 255) / 256, 256>>>(gc_src, gc_dst);
    k_aggsum <<<(N_CELL * 32) / 256, 256>>>(x_gene);
    k_gemm   <<<(N_CELL + BM - 1) / BM, 256>>>(x_cell, Wl, Wr, out);
    k_bnstats<<<1, 128>>>();
    k_norm   <<<(N_CELL * DIM / 4 + 255) / 256, 256>>>(out);
}

// round 2
// speedup vs baseline: 1.2599x; 1.2599x over previous
#include <cuda_runtime.h>
#include <cuda_bf16.h>

#define N_CELL  60000
#define N_GENE  4000
#define DIM     128
#define E_EDGES 1500000
#define EPS_BN  1e-5f
#define SCAN_B  ((N_CELL + 1023) / 1024)   // 59

// ---------------- scratch (static __device__, no allocation) ----------------
__device__ int   g_hist[N_CELL];
__device__ int   g_off [N_CELL + 1];
__device__ int   g_cur [N_CELL];          // also reused as scan temp
__device__ int   g_bsum[64];
__device__ int   g_boff[64];
__device__ int   g_csr [E_EDGES];
__device__ float g_y   [(size_t)N_GENE * DIM];   // x_gene @ Wl
__device__ float g_agg [(size_t)N_CELL * DIM];   // mean-aggregated y
__device__ float g_colsum[DIM];
__device__ float g_colsq [DIM];
__device__ float g_mu [DIM];
__device__ float g_rs [DIM];

// ---------------- 0: zero counters/stats ----------------
__global__ void k_zero() {
    int i = blockIdx.x * blockDim.x + threadIdx.x;
    if (i < N_CELL) g_hist[i] = 0;
    if (i < DIM) { g_colsum[i] = 0.f; g_colsq[i] = 0.f; }
}

// ---------------- 1: histogram of edge destinations ----------------
__global__ void k_hist(const int* __restrict__ dst) {
    int i = blockIdx.x * blockDim.x + threadIdx.x;
    if (i < E_EDGES) atomicAdd(&g_hist[dst[i]], 1);
}

// ---------------- 2a: per-block inclusive scan (59 blocks x 1024) ----------------
__global__ void k_scan1() {
    __shared__ int wsum[32];
    int t = threadIdx.x, lane = t & 31, wid = t >> 5;
    int i = blockIdx.x * 1024 + t;
    int v = (i < N_CELL) ? g_hist[i] : 0;
    int x = v;
    #pragma unroll
    for (int o = 1; o < 32; o <<= 1) {
        int y = __shfl_up_sync(0xffffffffu, x, o);
        if (lane >= o) x += y;
    }
    if (lane == 31) wsum[wid] = x;
    __syncthreads();
    if (wid == 0) {
        int w = wsum[lane];
        #pragma unroll
        for (int o = 1; o < 32; o <<= 1) {
            int y = __shfl_up_sync(0xffffffffu, w, o);
            if (lane >= o) w += y;
        }
        wsum[lane] = w;
    }
    __syncthreads();
    int incl = x + (wid ? wsum[wid - 1] : 0);
    if (i < N_CELL) g_cur[i] = incl;          // temp: local inclusive scan
    if (t == 1023) g_bsum[blockIdx.x] = incl; // block total
}

// ---------------- 2b: scan the 59 block sums (1 warp-pair) ----------------
__global__ void k_scan2() {
    int t = threadIdx.x, lane = t & 31, wid = t >> 5;  // 64 threads
    __shared__ int w0;
    int v = (t < SCAN_B) ? g_bsum[t] : 0;
    int x = v;
    #pragma unroll
    for (int o = 1; o < 32; o <<= 1) {
        int y = __shfl_up_sync(0xffffffffu, x, o);
        if (lane >= o) x += y;
    }
    if (t == 31) w0 = x;
    __syncthreads();
    int incl = x + (wid ? w0 : 0);
    if (t < SCAN_B) g_boff[t] = incl - v;     // exclusive
}

// ---------------- 2c: finalize offsets + write-cursors ----------------
__global__ void k_scan3() {
    int i = blockIdx.x * blockDim.x + threadIdx.x;
    if (i < N_CELL) {
        int incl = g_cur[i] + g_boff[i >> 10];
        g_off[i + 1] = incl;
        g_cur[i] = incl - g_hist[i];
        if (i == 0) g_off[0] = 0;
    }
}

// ---------------- 3: scatter edge source ids into CSR ----------------
__global__ void k_scatter(const int* __restrict__ src, const int* __restrict__ dst) {
    int i = blockIdx.x * blockDim.x + threadIdx.x;
    if (i < E_EDGES) {
        int d = dst[i];
        int p = atomicAdd(&g_cur[d], 1);
        g_csr[p] = src[i];
    }
}

// ---------------- 4: tiled 128x128 GEMM  C = A[M,128] @ B[128,128] ----------------
// FUSED: C += g_agg, accumulate BN column stats.  Bias bl is skipped (BN cancels it).
template<bool FUSED>
__global__ __launch_bounds__(256) void k_gemm128(
    const float* __restrict__ A,
    const float* __restrict__ B,
    float* __restrict__ C,
    int M)
{
    __shared__ float As[32][132];  // [k][m], padded
    __shared__ float Bs[32][128];  // [k][n]; reused for BN reduction

    int tid = threadIdx.x;
    int tr = tid >> 4;     // 0..15 row groups (8 rows each)
    int tc = tid & 15;     // 0..15 col groups (8 cols each)
    int m0 = blockIdx.x * 128;

    float acc[8][8];
    #pragma unroll
    for (int r = 0; r < 8; r++)
        #pragma unroll
        for (int c = 0; c < 8; c++) acc[r][c] = 0.f;

    for (int k0 = 0; k0 < DIM; k0 += 32) {
        // A tile: 128 rows x 32 k, float4 along k, store transposed
        #pragma unroll
        for (int t = 0; t < 4; t++) {
            int idx = tid + t * 256;
            int row = idx >> 3, q = idx & 7;
            float4 v = {0.f, 0.f, 0.f, 0.f};
            int gm = m0 + row;
            if (gm < M) v = *(const float4*)&A[(size_t)gm * DIM + k0 + q * 4];
            As[q * 4 + 0][row] = v.x;
            As[q * 4 + 1][row] = v.y;
            As[q * 4 + 2][row] = v.z;
            As[q * 4 + 3][row] = v.w;
        }
        // B tile: 32 k x 128 n
        #pragma unroll
        for (int t = 0; t < 4; t++) {
            int idx = tid + t * 256;
            int bk = idx >> 5, bn4 = idx & 31;
            *(float4*)&Bs[bk][bn4 * 4] =
                *(const float4*)&B[(size_t)(k0 + bk) * DIM + bn4 * 4];
        }
        __syncthreads();

        #pragma unroll
        for (int kk = 0; kk < 32; kk++) {
            float a[8], b[8];
            *(float4*)&a[0] = *(const float4*)&As[kk][tr * 8];
            *(float4*)&a[4] = *(const float4*)&As[kk][tr * 8 + 4];
            *(float4*)&b[0] = *(const float4*)&Bs[kk][tc * 8];
            *(float4*)&b[4] = *(const float4*)&Bs[kk][tc * 8 + 4];
            #pragma unroll
            for (int r = 0; r < 8; r++)
                #pragma unroll
                for (int c = 0; c < 8; c++)
                    acc[r][c] += a[r] * b[c];
        }
        __syncthreads();
    }

    if (!FUSED) {
        #pragma unroll
        for (int r = 0; r < 8; r++) {
            int gm = m0 + tr * 8 + r;
            if (gm < M) {
                #pragma unroll
                for (int c4 = 0; c4 < 2; c4++) {
                    float4 o = {acc[r][c4*4+0], acc[r][c4*4+1],
                                acc[r][c4*4+2], acc[r][c4*4+3]};
                    *(float4*)&C[(size_t)gm * DIM + tc * 8 + c4 * 4] = o;
                }
            }
        }
        return;
    }

    // FUSED epilogue: add aggregated term, store, per-column sum/sumsq
    float s[8], q[8];
    #pragma unroll
    for (int c = 0; c < 8; c++) { s[c] = 0.f; q[c] = 0.f; }
    #pragma unroll
    for (int r = 0; r < 8; r++) {
        int gm = m0 + tr * 8 + r;
        if (gm < M) {
            #pragma unroll
            for (int c4 = 0; c4 < 2; c4++) {
                float4 ag = *(const float4*)&g_agg[(size_t)gm * DIM + tc * 8 + c4 * 4];
                float v0 = acc[r][c4*4+0] + ag.x;
                float v1 = acc[r][c4*4+1] + ag.y;
                float v2 = acc[r][c4*4+2] + ag.z;
                float v3 = acc[r][c4*4+3] + ag.w;
                float4 o = {v0, v1, v2, v3};
                *(float4*)&C[(size_t)gm * DIM + tc * 8 + c4 * 4] = o;
                s[c4*4+0] += v0; q[c4*4+0] += v0 * v0;
                s[c4*4+1] += v1; q[c4*4+1] += v1 * v1;
                s[c4*4+2] += v2; q[c4*4+2] += v2 * v2;
                s[c4*4+3] += v3; q[c4*4+3] += v3 * v3;
            }
        }
    }
    __syncthreads();   // Bs no longer needed; reuse rows 0..15 for sum, 16..31 for sq
    #pragma unroll
    for (int c = 0; c < 8; c++) {
        Bs[tr][tc * 8 + c]      = s[c];
        Bs[16 + tr][tc * 8 + c] = q[c];
    }
    __syncthreads();
    if (tid < DIM) {
        float ss = 0.f, qq = 0.f;
        #pragma unroll
        for (int r = 0; r < 16; r++) { ss += Bs[r][tid]; qq += Bs[16 + r][tid]; }
        atomicAdd(&g_colsum[tid], ss);
        atomicAdd(&g_colsq[tid], qq);
    }
}

// ---------------- 5: per-cell neighbor mean of y (1 warp / cell) ----------------
__global__ void k_aggsum() {
    int w    = (blockIdx.x * blockDim.x + threadIdx.x) >> 5;
    int lane = threadIdx.x & 31;
    if (w >= N_CELL) return;
    int s = g_off[w], e = g_off[w + 1];
    const float4* yv = (const float4*)g_y;
    float4 a0 = {0.f,0.f,0.f,0.f}, a1 = {0.f,0.f,0.f,0.f};
    float4 a2 = {0.f,0.f,0.f,0.f}, a3 = {0.f,0.f,0.f,0.f};
    int i = s;
    for (; i + 3 < e; i += 4) {
        int g0 = __ldg(&g_csr[i]);
        int g1 = __ldg(&g_csr[i + 1]);
        int g2 = __ldg(&g_csr[i + 2]);
        int g3 = __ldg(&g_csr[i + 3]);
        float4 v0 = __ldg(&yv[(size_t)g0 * 32 + lane]);
        float4 v1 = __ldg(&yv[(size_t)g1 * 32 + lane]);
        float4 v2 = __ldg(&yv[(size_t)g2 * 32 + lane]);
        float4 v3 = __ldg(&yv[(size_t)g3 * 32 + lane]);
        a0.x += v0.x; a0.y += v0.y; a0.z += v0.z; a0.w += v0.w;
        a1.x += v1.x; a1.y += v1.y; a1.z += v1.z; a1.w += v1.w;
        a2.x += v2.x; a2.y += v2.y; a2.z += v2.z; a2.w += v2.w;
        a3.x += v3.x; a3.y += v3.y; a3.z += v3.z; a3.w += v3.w;
    }
    for (; i < e; i++) {
        int g0 = __ldg(&g_csr[i]);
        float4 v0 = __ldg(&yv[(size_t)g0 * 32 + lane]);
        a0.x += v0.x; a0.y += v0.y; a0.z += v0.z; a0.w += v0.w;
    }
    float inv = 1.f / (float)max(e - s, 1);
    float4 r;
    r.x = (a0.x + a1.x + a2.x + a3.x) * inv;
    r.y = (a0.y + a1.y + a2.y + a3.y) * inv;
    r.z = (a0.z + a1.z + a2.z + a3.z) * inv;
    r.w = (a0.w + a1.w + a2.w + a3.w) * inv;
    ((float4*)g_agg)[(size_t)w * 32 + lane] = r;
}

// ---------------- 6: finalize BN stats ----------------
__global__ void k_bnstats() {
    int n = threadIdx.x;
    if (n < DIM) {
        float mu  = g_colsum[n] / (float)N_CELL;
        float var = g_colsq[n] / (float)N_CELL - mu * mu;
        g_mu[n] = mu;
        g_rs[n] = rsqrtf(var + EPS_BN);
    }
}

// ---------------- 7: normalize in place ----------------
__global__ void k_norm(float* __restrict__ out) {
    int i = blockIdx.x * blockDim.x + threadIdx.x;   // float4 index
    const int total = N_CELL * DIM / 4;
    if (i < total) {
        float4 v  = ((float4*)out)[i];
        int c4 = i & 31;
        float4 mu = ((const float4*)g_mu)[c4];
        float4 rs = ((const float4*)g_rs)[c4];
        v.x = (v.x - mu.x) * rs.x;
        v.y = (v.y - mu.y) * rs.y;
        v.z = (v.z - mu.z) * rs.z;
        v.w = (v.w - mu.w) * rs.w;
        ((float4*)out)[i] = v;
    }
}

// ---------------- launch ----------------
extern "C" void kernel_launch(void* const* d_in, const int* in_sizes, int n_in,
                              void* d_out, int out_size) {
    const float* x_cell = (const float*)d_in[0];
    const float* x_gene = (const float*)d_in[1];
    const float* Wl_gc  = (const float*)d_in[2];
    // d_in[3] = bl_gc (bias cancels under BatchNorm -> unused)
    const float* Wr_gc  = (const float*)d_in[4];
    // d_in[5..7] = cg-layer weights (dead code in reference)
    const int* gc_src = (const int*)d_in[8];
    const int* gc_dst = (const int*)d_in[9];
    // d_in[10..11] = cg edges (dead)
    float* out = (float*)d_out;

    const float* Wl = Wl_gc + DIM * DIM;   // layer index L-1 = 1
    const float* Wr = Wr_gc + DIM * DIM;

    float* g_y_p;   cudaGetSymbolAddress((void**)&g_y_p,  g_y);

    k_zero   <<<(N_CELL + 255) / 256, 256>>>();
    k_hist   <<<(E_EDGES + 255) / 256, 256>>>(gc_dst);
    k_scan1  <<<SCAN_B, 1024>>>();
    k_scan2  <<<1, 64>>>();
    k_scan3  <<<(N_CELL + 255) / 256, 256>>>();
    k_scatter<<<(E_EDGES + 255) / 256, 256>>>(gc_src, gc_dst);
    // y = x_gene @ Wl  (tiny; makes the agg side GEMM-free)
    k_gemm128<false><<<(N_GENE + 127) / 128, 256>>>(x_gene, Wl, g_y_p, N_GENE);
    k_aggsum <<<(N_CELL * 32 + 255) / 256, 256>>>();
    // out = agg + x_cell @ Wr, with fused BN stats
    k_gemm128<true><<<(N_CELL + 127) / 128, 256>>>(x_cell, Wr, out, N_CELL);
    k_bnstats<<<1, 128>>>();
    k_norm   <<<(N_CELL * DIM / 4 + 255) / 256, 256>>>(out);
}

// round 3
// speedup vs baseline: 1.4939x; 1.1857x over previous
#include <cuda_runtime.h>
#include <cuda_fp16.h>

#define N_CELL  60000
#define N_GENE  4000
#define DIM     128
#define E_EDGES 1500000
#define EPS_BN  1e-5f
#define SCAN_B  ((N_CELL + 1023) / 1024)   // 59

#define PADH 136   // half stride for As/Bs in mma kernel (17*8: ldmatrix-aligned)
#define PADF 132   // float stride for Ds
#define MMA_SMEM (2 * 128 * PADH * 2 + 8192)   // As+Bs fp16 + 8KB reduce buf

// ---------------- scratch (static __device__, no allocation) ----------------
__device__ int    g_hist[N_CELL];
__device__ int    g_off [N_CELL + 1];
__device__ int    g_cur [N_CELL];
__device__ int    g_bsum[64];
__device__ int    g_boff[64];
__device__ int    g_csr [E_EDGES];
__device__ __half g_y   [(size_t)N_GENE * DIM];   // fp16(x_gene @ Wl)
__device__ float  g_agg [(size_t)N_CELL * DIM];   // mean-aggregated y (fp32)
__device__ float  g_colsum[DIM];
__device__ float  g_colsq [DIM];

// ---------------- 0: zero counters/stats ----------------
__global__ void k_zero() {
    int i = blockIdx.x * blockDim.x + threadIdx.x;
    if (i < N_CELL) g_hist[i] = 0;
    if (i < DIM) { g_colsum[i] = 0.f; g_colsq[i] = 0.f; }
}

// ---------------- 1: histogram of edge destinations (x4 vectorized) ----------------
__global__ void k_hist(const int4* __restrict__ dst) {
    int i = blockIdx.x * blockDim.x + threadIdx.x;
    if (i < E_EDGES / 4) {
        int4 d = __ldg(&dst[i]);
        atomicAdd(&g_hist[d.x], 1);
        atomicAdd(&g_hist[d.y], 1);
        atomicAdd(&g_hist[d.z], 1);
        atomicAdd(&g_hist[d.w], 1);
    }
}

// ---------------- 2a: per-block inclusive scan ----------------
__global__ void k_scan1() {
    __shared__ int wsum[32];
    int t = threadIdx.x, lane = t & 31, wid = t >> 5;
    int i = blockIdx.x * 1024 + t;
    int v = (i < N_CELL) ? g_hist[i] : 0;
    int x = v;
    #pragma unroll
    for (int o = 1; o < 32; o <<= 1) {
        int y = __shfl_up_sync(0xffffffffu, x, o);
        if (lane >= o) x += y;
    }
    if (lane == 31) wsum[wid] = x;
    __syncthreads();
    if (wid == 0) {
        int w = wsum[lane];
        #pragma unroll
        for (int o = 1; o < 32; o <<= 1) {
            int y = __shfl_up_sync(0xffffffffu, w, o);
            if (lane >= o) w += y;
        }
        wsum[lane] = w;
    }
    __syncthreads();
    int incl = x + (wid ? wsum[wid - 1] : 0);
    if (i < N_CELL) g_cur[i] = incl;
    if (t == 1023) g_bsum[blockIdx.x] = incl;
}

// ---------------- 2b: scan the 59 block sums ----------------
__global__ void k_scan2() {
    int t = threadIdx.x, lane = t & 31, wid = t >> 5;  // 64 threads
    __shared__ int w0;
    int v = (t < SCAN_B) ? g_bsum[t] : 0;
    int x = v;
    #pragma unroll
    for (int o = 1; o < 32; o <<= 1) {
        int y = __shfl_up_sync(0xffffffffu, x, o);
        if (lane >= o) x += y;
    }
    if (t == 31) w0 = x;
    __syncthreads();
    int incl = x + (wid ? w0 : 0);
    if (t < SCAN_B) g_boff[t] = incl - v;
}

// ---------------- 2c: finalize offsets + write-cursors ----------------
__global__ void k_scan3() {
    int i = blockIdx.x * blockDim.x + threadIdx.x;
    if (i < N_CELL) {
        int incl = g_cur[i] + g_boff[i >> 10];
        g_off[i + 1] = incl;
        g_cur[i] = incl - g_hist[i];
        if (i == 0) g_off[0] = 0;
    }
}

// ---------------- 3: scatter edge source ids into CSR ----------------
__global__ void k_scatter(const int* __restrict__ src, const int* __restrict__ dst) {
    int i = blockIdx.x * blockDim.x + threadIdx.x;
    if (i < E_EDGES) {
        int d = dst[i];
        int p = atomicAdd(&g_cur[d], 1);
        g_csr[p] = src[i];
    }
}

// ---------------- 4: small fp32 GEMM  g_y = fp16(x_gene @ Wl) ----------------
__global__ __launch_bounds__(256) void k_ygemm(
    const float* __restrict__ A,
    const float* __restrict__ B,
    int M)
{
    __shared__ float As[32][132];
    __shared__ float Bs[32][128];

    int tid = threadIdx.x;
    int tr = tid >> 4, tc = tid & 15;
    int m0 = blockIdx.x * 128;

    float acc[8][8];
    #pragma unroll
    for (int r = 0; r < 8; r++)
        #pragma unroll
        for (int c = 0; c < 8; c++) acc[r][c] = 0.f;

    for (int k0 = 0; k0 < DIM; k0 += 32) {
        #pragma unroll
        for (int t = 0; t < 4; t++) {
            int idx = tid + t * 256;
            int row = idx >> 3, q = idx & 7;
            float4 v = {0.f, 0.f, 0.f, 0.f};
            int gm = m0 + row;
            if (gm < M) v = *(const float4*)&A[(size_t)gm * DIM + k0 + q * 4];
            As[q * 4 + 0][row] = v.x;
            As[q * 4 + 1][row] = v.y;
            As[q * 4 + 2][row] = v.z;
            As[q * 4 + 3][row] = v.w;
        }
        #pragma unroll
        for (int t = 0; t < 4; t++) {
            int idx = tid + t * 256;
            int bk = idx >> 5, bn4 = idx & 31;
            *(float4*)&Bs[bk][bn4 * 4] =
                *(const float4*)&B[(size_t)(k0 + bk) * DIM + bn4 * 4];
        }
        __syncthreads();
        #pragma unroll
        for (int kk = 0; kk < 32; kk++) {
            float a[8], b[8];
            *(float4*)&a[0] = *(const float4*)&As[kk][tr * 8];
            *(float4*)&a[4] = *(const float4*)&As[kk][tr * 8 + 4];
            *(float4*)&b[0] = *(const float4*)&Bs[kk][tc * 8];
            *(float4*)&b[4] = *(const float4*)&Bs[kk][tc * 8 + 4];
            #pragma unroll
            for (int r = 0; r < 8; r++)
                #pragma unroll
                for (int c = 0; c < 8; c++)
                    acc[r][c] += a[r] * b[c];
        }
        __syncthreads();
    }
    #pragma unroll
    for (int r = 0; r < 8; r++) {
        int gm = m0 + tr * 8 + r;
        if (gm < M) {
            #pragma unroll
            for (int c2 = 0; c2 < 4; c2++) {
                __half2 h = __floats2half2_rn(acc[r][c2 * 2], acc[r][c2 * 2 + 1]);
                *(__half2*)&g_y[(size_t)gm * DIM + tc * 8 + c2 * 2] = h;
            }
        }
    }
}

// ---------------- 5: per-cell neighbor mean of fp16 y (1 warp / cell) ----------------
__global__ void k_aggsum() {
    int w    = (blockIdx.x * blockDim.x + threadIdx.x) >> 5;
    int lane = threadIdx.x & 31;
    if (w >= N_CELL) return;
    int s = g_off[w], e = g_off[w + 1];
    const uint2* yv = (const uint2*)g_y;   // 4 halves / lane / row
    float ax0=0.f, ax1=0.f, ax2=0.f, ax3=0.f;
    float bx0=0.f, bx1=0.f, bx2=0.f, bx3=0.f;
    float cx0=0.f, cx1=0.f, cx2=0.f, cx3=0.f;
    float dx0=0.f, dx1=0.f, dx2=0.f, dx3=0.f;
    int i = s;
    for (; i + 3 < e; i += 4) {
        int g0 = __ldg(&g_csr[i]);
        int g1 = __ldg(&g_csr[i + 1]);
        int g2 = __ldg(&g_csr[i + 2]);
        int g3 = __ldg(&g_csr[i + 3]);
        uint2 u0 = __ldg(&yv[(size_t)g0 * 32 + lane]);
        uint2 u1 = __ldg(&yv[(size_t)g1 * 32 + lane]);
        uint2 u2 = __ldg(&yv[(size_t)g2 * 32 + lane]);
        uint2 u3 = __ldg(&yv[(size_t)g3 * 32 + lane]);
        float2 p, q;
        p = __half22float2(*(__half2*)&u0.x); q = __half22float2(*(__half2*)&u0.y);
        ax0 += p.x; ax1 += p.y; ax2 += q.x; ax3 += q.y;
        p = __half22float2(*(__half2*)&u1.x); q = __half22float2(*(__half2*)&u1.y);
        bx0 += p.x; bx1 += p.y; bx2 += q.x; bx3 += q.y;
        p = __half22float2(*(__half2*)&u2.x); q = __half22float2(*(__half2*)&u2.y);
        cx0 += p.x; cx1 += p.y; cx2 += q.x; cx3 += q.y;
        p = __half22float2(*(__half2*)&u3.x); q = __half22float2(*(__half2*)&u3.y);
        dx0 += p.x; dx1 += p.y; dx2 += q.x; dx3 += q.y;
    }
    for (; i < e; i++) {
        int g0 = __ldg(&g_csr[i]);
        uint2 u0 = __ldg(&yv[(size_t)g0 * 32 + lane]);
        float2 p = __half22float2(*(__half2*)&u0.x);
        float2 q = __half22float2(*(__half2*)&u0.y);
        ax0 += p.x; ax1 += p.y; ax2 += q.x; ax3 += q.y;
    }
    float inv = 1.f / (float)max(e - s, 1);
    float4 r;
    r.x = (ax0 + bx0 + cx0 + dx0) * inv;
    r.y = (ax1 + bx1 + cx1 + dx1) * inv;
    r.z = (ax2 + bx2 + cx2 + dx2) * inv;
    r.w = (ax3 + bx3 + cx3 + dx3) * inv;
    ((float4*)g_agg)[(size_t)w * 32 + lane] = r;
}

// ---------------- 6: fp16 tensor-core GEMM  out = x_cell@Wr + g_agg, fused BN stats ----
__device__ __forceinline__ unsigned su32(const void* p) {
    return (unsigned)__cvta_generic_to_shared(p);
}
__device__ __forceinline__ void ldsm4(unsigned a, unsigned& r0, unsigned& r1,
                                      unsigned& r2, unsigned& r3) {
    asm volatile("ldmatrix.sync.aligned.m8n8.x4.shared.b16 {%0,%1,%2,%3}, [%4];"
                 : "=r"(r0), "=r"(r1), "=r"(r2), "=r"(r3) : "r"(a));
}
__device__ __forceinline__ void ldsm4t(unsigned a, unsigned& r0, unsigned& r1,
                                       unsigned& r2, unsigned& r3) {
    asm volatile("ldmatrix.sync.aligned.m8n8.x4.trans.shared.b16 {%0,%1,%2,%3}, [%4];"
                 : "=r"(r0), "=r"(r1), "=r"(r2), "=r"(r3) : "r"(a));
}
__device__ __forceinline__ void mma16816(float* d, const unsigned* a, const unsigned* b) {
    asm volatile(
        "mma.sync.aligned.m16n8k16.row.col.f32.f16.f16.f32 "
        "{%0,%1,%2,%3}, {%4,%5,%6,%7}, {%8,%9}, {%0,%1,%2,%3};"
        : "+f"(d[0]), "+f"(d[1]), "+f"(d[2]), "+f"(d[3])
        : "r"(a[0]), "r"(a[1]), "r"(a[2]), "r"(a[3]), "r"(b[0]), "r"(b[1]));
}

__global__ __launch_bounds__(256) void k_mma(
    const float* __restrict__ x_cell,
    const float* __restrict__ Wr,
    float* __restrict__ out,
    int M)
{
    extern __shared__ char smem[];
    __half* As = (__half*)smem;                       // [128][PADH]
    __half* Bs = (__half*)smem + 128 * PADH;          // [128][PADH], stored [k][n]
    float*  Ds = (float*)smem;                        // [128][PADF] (aliases As/Bs)
    float*  red = (float*)(smem + 2 * 128 * PADH * 2);// 2048 floats

    int tid  = threadIdx.x;
    int warp = tid >> 5, lane = tid & 31;
    int wm = warp & 3, wn = warp >> 2;   // 4 x 2 warp grid; warp tile 32m x 64n
    int m0 = blockIdx.x * 128;

    // load A tile (fp32 -> fp16)
    #pragma unroll
    for (int it = 0; it < 16; it++) {
        int idx = tid + it * 256;
        int row = idx >> 5, q = idx & 31;
        float4 v = {0.f, 0.f, 0.f, 0.f};
        int gm = m0 + row;
        if (gm < M) v = *(const float4*)&x_cell[(size_t)gm * DIM + q * 4];
        *(__half2*)&As[row * PADH + q * 4]     = __floats2half2_rn(v.x, v.y);
        *(__half2*)&As[row * PADH + q * 4 + 2] = __floats2half2_rn(v.z, v.w);
    }
    // load B tile [k][n] (fp32 -> fp16), no transpose (ldmatrix.trans handles it)
    #pragma unroll
    for (int it = 0; it < 16; it++) {
        int idx = tid + it * 256;
        int k = idx >> 5, n4 = idx & 31;
        float4 v = *(const float4*)&Wr[(size_t)k * DIM + n4 * 4];
        *(__half2*)&Bs[k * PADH + n4 * 4]     = __floats2half2_rn(v.x, v.y);
        *(__half2*)&Bs[k * PADH + n4 * 4 + 2] = __floats2half2_rn(v.z, v.w);
    }
    __syncthreads();

    float acc[2][8][4];
    #pragma unroll
    for (int tm = 0; tm < 2; tm++)
        #pragma unroll
        for (int tn = 0; tn < 8; tn++)
            #pragma unroll
            for (int j = 0; j < 4; j++) acc[tm][tn][j] = 0.f;

    #pragma unroll
    for (int ks = 0; ks < 8; ks++) {
        unsigned a[2][4], b[8][2];
        #pragma unroll
        for (int tm = 0; tm < 2; tm++) {
            unsigned addr = su32(&As[(wm * 32 + tm * 16 + (lane & 15)) * PADH
                                     + ks * 16 + (lane >> 4) * 8]);
            ldsm4(addr, a[tm][0], a[tm][1], a[tm][2], a[tm][3]);
        }
        #pragma unroll
        for (int tp = 0; tp < 4; tp++) {   // pairs of n-tiles
            unsigned addr = su32(&Bs[(ks * 16 + (lane & 15)) * PADH
                                     + wn * 64 + tp * 16 + (lane >> 4) * 8]);
            ldsm4t(addr, b[tp * 2][0], b[tp * 2][1], b[tp * 2 + 1][0], b[tp * 2 + 1][1]);
        }
        #pragma unroll
        for (int tm = 0; tm < 2; tm++)
            #pragma unroll
            for (int tn = 0; tn < 8; tn++)
                mma16816(acc[tm][tn], a[tm], b[tn]);
    }

    __syncthreads();   // done reading As/Bs; reuse as Ds
    #pragma unroll
    for (int tm = 0; tm < 2; tm++) {
        int r0 = wm * 32 + tm * 16 + (lane >> 2);
        #pragma unroll
        for (int tn = 0; tn < 8; tn++) {
            int c = wn * 64 + tn * 8 + (lane & 3) * 2;
            *(float2*)&Ds[r0 * PADF + c]       = make_float2(acc[tm][tn][0], acc[tm][tn][1]);
            *(float2*)&Ds[(r0 + 8) * PADF + c] = make_float2(acc[tm][tn][2], acc[tm][tn][3]);
        }
    }
    __syncthreads();

    // uniform epilogue: += agg, BN stats, store
    int c4 = tid & 31;            // 4 columns per thread
    int rb = (tid >> 5) * 16;     // 16 rows per thread
    float s[4] = {0.f, 0.f, 0.f, 0.f};
    float q[4] = {0.f, 0.f, 0.f, 0.f};
    #pragma unroll
    for (int i = 0; i < 16; i++) {
        int r = rb + i, gm = m0 + r;
        if (gm < M) {
            float4 v  = *(float4*)&Ds[r * PADF + c4 * 4];
            float4 ag = *(const float4*)&g_agg[(size_t)gm * DIM + c4 * 4];
            v.x += ag.x; v.y += ag.y; v.z += ag.z; v.w += ag.w;
            *(float4*)&out[(size_t)gm * DIM + c4 * 4] = v;
            s[0] += v.x; q[0] += v.x * v.x;
            s[1] += v.y; q[1] += v.y * v.y;
            s[2] += v.z; q[2] += v.z * v.z;
            s[3] += v.w; q[3] += v.w * v.w;
        }
    }
    __syncthreads();   // Ds reads done before red (aliased region is separate, but keep order)
    #pragma unroll
    for (int c = 0; c < 4; c++) {
        red[(tid >> 5) * DIM + c4 * 4 + c]        = s[c];
        red[1024 + (tid >> 5) * DIM + c4 * 4 + c] = q[c];
    }
    __syncthreads();
    if (tid < DIM) {
        float ss = 0.f, qq = 0.f;
        #pragma unroll
        for (int r = 0; r < 8; r++) {
            ss += red[r * DIM + tid];
            qq += red[1024 + r * DIM + tid];
        }
        atomicAdd(&g_colsum[tid], ss);
        atomicAdd(&g_colsq[tid], qq);
    }
}

// ---------------- 7: normalize in place (BN stats finalized inline) ----------------
__global__ void k_norm(float* __restrict__ out) {
    int i = blockIdx.x * blockDim.x + threadIdx.x;   // float4 index
    const int total = N_CELL * DIM / 4;
    if (i < total) {
        int c = (i & 31) * 4;
        const float invN = 1.f / (float)N_CELL;
        float mu0 = g_colsum[c + 0] * invN, mu1 = g_colsum[c + 1] * invN;
        float mu2 = g_colsum[c + 2] * invN, mu3 = g_colsum[c + 3] * invN;
        float rs0 = rsqrtf(g_colsq[c + 0] * invN - mu0 * mu0 + EPS_BN);
        float rs1 = rsqrtf(g_colsq[c + 1] * invN - mu1 * mu1 + EPS_BN);
        float rs2 = rsqrtf(g_colsq[c + 2] * invN - mu2 * mu2 + EPS_BN);
        float rs3 = rsqrtf(g_colsq[c + 3] * invN - mu3 * mu3 + EPS_BN);
        float4 v = ((float4*)out)[i];
        v.x = (v.x - mu0) * rs0;
        v.y = (v.y - mu1) * rs1;
        v.z = (v.z - mu2) * rs2;
        v.w = (v.w - mu3) * rs3;
        ((float4*)out)[i] = v;
    }
}

// ---------------- launch ----------------
extern "C" void kernel_launch(void* const* d_in, const int* in_sizes, int n_in,
                              void* d_out, int out_size) {
    const float* x_cell = (const float*)d_in[0];
    const float* x_gene = (const float*)d_in[1];
    const float* Wl_gc  = (const float*)d_in[2];
    const float* Wr_gc  = (const float*)d_in[4];
    const int* gc_src = (const int*)d_in[8];
    const int* gc_dst = (const int*)d_in[9];
    float* out = (float*)d_out;

    const float* Wl = Wl_gc + DIM * DIM;   // layer L-1 = 1
    const float* Wr = Wr_gc + DIM * DIM;

    static bool attr_set = false;
    if (!attr_set) {
        cudaFuncSetAttribute(k_mma, cudaFuncAttributeMaxDynamicSharedMemorySize, MMA_SMEM);
        attr_set = true;
    }

    k_zero   <<<(N_CELL + 255) / 256, 256>>>();
    k_hist   <<<(E_EDGES / 4 + 255) / 256, 256>>>((const int4*)gc_dst);
    k_scan1  <<<SCAN_B, 1024>>>();
    k_scan2  <<<1, 64>>>();
    k_scan3  <<<(N_CELL + 255) / 256, 256>>>();
    k_scatter<<<(E_EDGES + 255) / 256, 256>>>(gc_src, gc_dst);
    k_ygemm  <<<(N_GENE + 127) / 128, 256>>>(x_gene, Wl, N_GENE);
    k_aggsum <<<(N_CELL * 32 + 255) / 256, 256>>>();
    k_mma    <<<(N_CELL + 127) / 128, 256, MMA_SMEM>>>(x_cell, Wr, out, N_CELL);
    k_norm   <<<(N_CELL * DIM / 4 + 255) / 256, 256>>>(out);
}